// round 9
// baseline (speedup 1.0000x reference)
#include <cuda_runtime.h>
#include <cuda_fp16.h>
#include <cstdint>

// ---- problem constants ----
#define BDIM 4
#define TDIM 4096
#define NTOK (BDIM * TDIM)      // 16384
#define DDIM 2048
#define KDIM 2048               // H*2*E
#define TS 100000
#define VOCAB 50257
#define M0 20011
#define M1 30011
#define M2 40009

// ---- device scratch (allocation-free rule) ----
__device__ __half g_e[(size_t)NTOK * KDIM];
__device__ __half g_w[(size_t)DDIM * KDIM];
__device__ float  g_v[(size_t)NTOK * DDIM];

// ============================================================================
// Baseline-PTX helpers (NO tcgen05 — harness compiles plain sm_103)
// ============================================================================
__device__ __forceinline__ uint32_t smem_to_u32(const void* p) {
    uint32_t a;
    asm("{ .reg .u64 t; cvta.to.shared.u64 t, %1; cvt.u32.u64 %0, t; }"
        : "=r"(a) : "l"(p));
    return a;
}
__device__ __forceinline__ void cp_async16(uint32_t smem_addr, const void* gptr) {
    asm volatile("cp.async.cg.shared.global [%0], [%1], 16;"
                 :: "r"(smem_addr), "l"(gptr) : "memory");
}
__device__ __forceinline__ void cp_commit() {
    asm volatile("cp.async.commit_group;" ::: "memory");
}
template <int N>
__device__ __forceinline__ void cp_wait_group() {
    asm volatile("cp.async.wait_group %0;" :: "n"(N) : "memory");
}
__device__ __forceinline__ void ldsm_x4(uint32_t* r, uint32_t addr) {
    asm volatile("ldmatrix.sync.aligned.m8n8.x4.shared.b16 {%0,%1,%2,%3}, [%4];"
                 : "=r"(r[0]), "=r"(r[1]), "=r"(r[2]), "=r"(r[3]) : "r"(addr));
}
__device__ __forceinline__ void mma_f16(float* d, const uint32_t* a,
                                        uint32_t b0, uint32_t b1) {
    asm volatile(
        "mma.sync.aligned.m16n8k16.row.col.f32.f16.f16.f32 "
        "{%0,%1,%2,%3}, {%4,%5,%6,%7}, {%8,%9}, {%0,%1,%2,%3};"
        : "+f"(d[0]), "+f"(d[1]), "+f"(d[2]), "+f"(d[3])
        : "r"(a[0]), "r"(a[1]), "r"(a[2]), "r"(a[3]), "r"(b0), "r"(b1));
}

// ============================================================================
// Kernel 0: convert Wv fp32 -> fp16
// ============================================================================
__global__ __launch_bounds__(256) void wconv_kernel(const float* __restrict__ Wv)
{
    size_t base = ((size_t)blockIdx.x * 256 + threadIdx.x) * 8;
    float4 x0 = *reinterpret_cast<const float4*>(Wv + base);
    float4 x1 = *reinterpret_cast<const float4*>(Wv + base + 4);
    float xs[8] = {x0.x, x0.y, x0.z, x0.w, x1.x, x1.y, x1.z, x1.w};
    __half h[8];
    #pragma unroll
    for (int j = 0; j < 8; j++) h[j] = __float2half_rn(xs[j]);
    *reinterpret_cast<uint4*>(g_w + base) = *reinterpret_cast<uint4*>(h);
}

// ============================================================================
// Kernel 1: hash + gather -> fp16 e rows.  One block per token.
// ============================================================================
__global__ __launch_bounds__(256) void gather_kernel(
    const int* __restrict__ input_ids,
    const float* __restrict__ tables2,
    const float* __restrict__ tables3)
{
    int t = blockIdx.x;
    int tid = threadIdx.x;
    __shared__ int s_i2, s_i3;
    if (tid == 0) {
        int b = t / TDIM;
        int tt = t % TDIM;
        const int* row = input_ids + (size_t)b * TDIM;
        int id0 = row[tt];
        id0 = id0 < 0 ? 0 : (id0 > VOCAB - 1 ? VOCAB - 1 : id0);
        int s1 = 0, s2 = 0;
        if (tt >= 1) { s1 = row[tt - 1]; s1 = s1 < 0 ? 0 : (s1 > VOCAB - 1 ? VOCAB - 1 : s1); }
        if (tt >= 2) { s2 = row[tt - 2]; s2 = s2 < 0 ? 0 : (s2 > VOCAB - 1 ? VOCAB - 1 : s2); }
        int hash2 = (id0 * M0) ^ (s1 * M1);
        int hash3 = hash2 ^ (s2 * M2);
        int i2 = hash2 % TS; if (i2 < 0) i2 = 0;
        int i3 = hash3 % TS; if (i3 < 0) i3 = 0;
        s_i2 = i2; s_i3 = i3;
    }
    __syncthreads();
    int i2 = s_i2, i3 = s_i3;

    int f0 = tid * 8;
    int seg = f0 >> 8;
    int off = f0 & 255;
    const float* src = (seg < 4)
        ? tables2 + ((size_t)seg * TS + i2) * 256 + off
        : tables3 + ((size_t)(seg - 4) * TS + i3) * 256 + off;
    float4 x0 = *reinterpret_cast<const float4*>(src);
    float4 x1 = *reinterpret_cast<const float4*>(src + 4);
    float xs[8] = {x0.x, x0.y, x0.z, x0.w, x1.x, x1.y, x1.z, x1.w};
    __half h[8];
    #pragma unroll
    for (int j = 0; j < 8; j++) h[j] = __float2half_rn(xs[j]);
    *reinterpret_cast<uint4*>(g_e + (size_t)t * KDIM + f0) =
        *reinterpret_cast<uint4*>(h);
}

// ============================================================================
// Kernel 2: fp16 GEMM via mma.sync (HMMA), fp32 accum in registers.
//   C[m][n] = sum_k e[m][k] * Wv[n][k]   both K-contiguous (NT)
//   CTA tile 128x128, k-chunk 32, 4-stage cp.async pipeline (dist 3).
//   __launch_bounds__(256, 2): cap regs at 128 -> 2 CTAs/SM for latency hiding.
// Stage (16KB): A @0: 128 rows x 64B (32 fp16); B @8192 same.
//   16B-unit swizzle: c ^= (row>>1)&3.
// ============================================================================
#define NK (KDIM / 32)            // 64 chunks
#define STAGES 4
#define STAGE_BYTES 16384
#define GEMM_SMEM (STAGES * STAGE_BYTES)   // 65536

__global__ __launch_bounds__(256, 2) void gemm_kernel()
{
    extern __shared__ char smem[];
    const uint32_t sbase = smem_to_u32(smem);
    const int tid = threadIdx.x;
    const int lane = tid & 31;
    const int wid = tid >> 5;
    const int warpM = wid & 1;        // 2 warps in M
    const int warpN = wid >> 1;       // 4 warps in N
    const int m0 = blockIdx.y * 128;
    const int n0 = blockIdx.x * 128;

    // ---- per-thread cp.async mapping (4 x 16B per stage) ----
    const __half* src[4];
    uint32_t dstoff[4];
    #pragma unroll
    for (int i = 0; i < 4; i++) {
        int g = tid + i * 256;               // 0..1023
        int isB = g >= 512;
        int gl = g & 511;
        int row = gl >> 2;                   // 0..127
        int ch = gl & 3;                     // 16B unit within 64B row
        const __half* base = isB ? g_w : g_e;
        int rowg = (isB ? n0 : m0) + row;
        src[i] = base + (size_t)rowg * KDIM + ch * 8;
        dstoff[i] = (isB ? 8192u : 0u) + (uint32_t)row * 64u
                  + (uint32_t)((ch ^ ((row >> 1) & 3)) << 4);
    }

    // ---- ldmatrix address components (verified geometry) ----
    const int l15 = lane & 15;
    const int lhi = lane >> 4;
    const int s = (l15 >> 1) & 3;
    const uint32_t aRowBase = (uint32_t)(warpM * 64 + l15) * 64u;
    const uint32_t bRowBase = (uint32_t)(warpN * 32 + l15) * 64u;
    const uint32_t chj[2] = { (uint32_t)((lhi ^ s) << 4),
                              (uint32_t)(((2 + lhi) ^ s) << 4) };

    float acc[4][4][4];
    #pragma unroll
    for (int mf = 0; mf < 4; mf++)
        #pragma unroll
        for (int nf = 0; nf < 4; nf++)
            #pragma unroll
            for (int q = 0; q < 4; q++) acc[mf][nf][q] = 0.f;

    // ---- prologue: preload stages 0..2 ----
    #pragma unroll
    for (int st = 0; st < 3; st++) {
        uint32_t sb = sbase + st * STAGE_BYTES;
        #pragma unroll
        for (int i = 0; i < 4; i++)
            cp_async16(sb + dstoff[i], src[i] + st * 32);
        cp_commit();
    }

    for (int kt = 0; kt < NK; kt++) {
        if (kt <= NK - 3)      cp_wait_group<2>();
        else if (kt == NK - 2) cp_wait_group<1>();
        else                   cp_wait_group<0>();
        __syncthreads();

        if (kt + 3 < NK) {
            uint32_t sb = sbase + ((kt + 3) & 3) * STAGE_BYTES;
            #pragma unroll
            for (int i = 0; i < 4; i++)
                cp_async16(sb + dstoff[i], src[i] + (kt + 3) * 32);
            cp_commit();
        }

        const uint32_t sb = sbase + (kt & 3) * STAGE_BYTES;
        #pragma unroll
        for (int j = 0; j < 2; j++) {        // two k16 halves of the k32 chunk
            const uint32_t co = chj[j];
            uint32_t a[4][4];
            uint32_t b[2][4];
            #pragma unroll
            for (int nh = 0; nh < 2; nh++)
                ldsm_x4(b[nh], sb + 8192u + bRowBase + (uint32_t)(nh * 1024) + co);
            #pragma unroll
            for (int mf = 0; mf < 4; mf++)
                ldsm_x4(a[mf], sb + aRowBase + (uint32_t)(mf * 1024) + co);

            #pragma unroll
            for (int mf = 0; mf < 4; mf++)
                #pragma unroll
                for (int nf = 0; nf < 4; nf++) {
                    const int nh = nf >> 1, su = nf & 1;
                    mma_f16(acc[mf][nf], a[mf], b[nh][su], b[nh][su + 2]);
                }
        }
    }

    // ---- epilogue: write fp32 result ----
    const int grp = lane >> 2;
    const int q2 = (lane & 3) * 2;
    #pragma unroll
    for (int mf = 0; mf < 4; mf++) {
        #pragma unroll
        for (int nf = 0; nf < 4; nf++) {
            int r = m0 + warpM * 64 + mf * 16 + grp;
            int c = n0 + warpN * 32 + nf * 8 + q2;
            *reinterpret_cast<float2*>(g_v + (size_t)r * DDIM + c) =
                make_float2(acc[mf][nf][0], acc[mf][nf][1]);
            *reinterpret_cast<float2*>(g_v + (size_t)(r + 8) * DDIM + c) =
                make_float2(acc[mf][nf][2], acc[mf][nf][3]);
        }
    }
}

// ============================================================================
// Kernel 3: gating
// ============================================================================
__global__ __launch_bounds__(256) void gate_kernel(
    const float* __restrict__ hidden,
    const float* __restrict__ wh,
    const float* __restrict__ wv,
    float* __restrict__ out)
{
    int t = blockIdx.x;
    int tid = threadIdx.x;
    const float* h = hidden + (size_t)t * DDIM;
    const float* v = g_v + (size_t)t * DDIM;

    float4 v4[2];
    float shh = 0.f, svv = 0.f, shv = 0.f;
    #pragma unroll
    for (int r = 0; r < 2; r++) {
        int q = tid + r * 256;
        float4 h4  = *reinterpret_cast<const float4*>(h + (size_t)q * 4);
        float4 x4  = *reinterpret_cast<const float4*>(v + (size_t)q * 4);
        float4 wh4 = *reinterpret_cast<const float4*>(wh + (size_t)q * 4);
        float4 wv4 = *reinterpret_cast<const float4*>(wv + (size_t)q * 4);
        v4[r] = x4;
        shh += h4.x * h4.x + h4.y * h4.y + h4.z * h4.z + h4.w * h4.w;
        svv += x4.x * x4.x + x4.y * x4.y + x4.z * x4.z + x4.w * x4.w;
        shv += (h4.x * wh4.x) * (x4.x * wv4.x)
             + (h4.y * wh4.y) * (x4.y * wv4.y)
             + (h4.z * wh4.z) * (x4.z * wv4.z)
             + (h4.w * wh4.w) * (x4.w * wv4.w);
    }

    #pragma unroll
    for (int o = 16; o > 0; o >>= 1) {
        shh += __shfl_down_sync(0xffffffffu, shh, o);
        svv += __shfl_down_sync(0xffffffffu, svv, o);
        shv += __shfl_down_sync(0xffffffffu, shv, o);
    }
    __shared__ float s0[8], s1[8], s2[8];
    int warp = tid >> 5, lane = tid & 31;
    if (lane == 0) { s0[warp] = shh; s1[warp] = svv; s2[warp] = shv; }
    __syncthreads();
    float thh = 0.f, tvv = 0.f, thv = 0.f;
    #pragma unroll
    for (int w = 0; w < 8; w++) { thh += s0[w]; tvv += s1[w]; thv += s2[w]; }

    const float eps = 1.1920928955078125e-7f;
    float rh = rsqrtf(thh * (1.f / DDIM) + eps);
    float rv = rsqrtf(tvv * (1.f / DDIM) + eps);
    float gate = thv * rh * rv * (1.f / 45.254833995939045f);
    float ga = fabsf(gate);
    ga = fmaxf(ga, 1e-6f);
    float gs = copysignf(sqrtf(ga), gate);
    float sig = 1.f / (1.f + expf(-gs));

    float* o = out + (size_t)t * DDIM;
    #pragma unroll
    for (int r = 0; r < 2; r++) {
        int q = tid + r * 256;
        float4 x = v4[r];
        x.x *= sig; x.y *= sig; x.z *= sig; x.w *= sig;
        *reinterpret_cast<float4*>(o + (size_t)q * 4) = x;
    }
}

// ---------------------------------------------------------------------------
extern "C" void kernel_launch(void* const* d_in, const int* in_sizes, int n_in,
                              void* d_out, int out_size)
{
    const float* hidden  = (const float*)d_in[0];
    const float* tables2 = (const float*)d_in[1];
    const float* tables3 = (const float*)d_in[2];
    const float* Wv      = (const float*)d_in[3];
    const float* wh      = (const float*)d_in[4];
    const float* wv      = (const float*)d_in[5];
    const int*   ids     = (const int*)d_in[6];
    float* out = (float*)d_out;

    static bool attr_set = false;
    if (!attr_set) {
        cudaFuncSetAttribute(gemm_kernel,
                             cudaFuncAttributeMaxDynamicSharedMemorySize, GEMM_SMEM);
        attr_set = true;
    }

    wconv_kernel<<<(DDIM * KDIM) / (256 * 8), 256>>>(Wv);
    gather_kernel<<<NTOK, 256>>>(ids, tables2, tables3);

    dim3 grid(DDIM / 128, NTOK / 128);   // (16, 128); x-major shares A in L2
    gemm_kernel<<<grid, 256, GEMM_SMEM>>>();

    gate_kernel<<<NTOK, 256>>>(hidden, wh, wv, out);
}

// round 10
// speedup vs baseline: 1.6551x; 1.6551x over previous
#include <cuda_runtime.h>
#include <cuda_fp16.h>
#include <cstdint>

// ---- problem constants ----
#define BDIM 4
#define TDIM 4096
#define NTOK (BDIM * TDIM)      // 16384
#define DDIM 2048
#define KDIM 2048               // H*2*E
#define TS 100000
#define VOCAB 50257
#define M0 20011
#define M1 30011
#define M2 40009

// ---- device scratch (allocation-free rule) ----
__device__ __half g_e[(size_t)NTOK * KDIM];
__device__ __half g_w[(size_t)DDIM * KDIM];
__device__ float  g_v[(size_t)NTOK * DDIM];

// ============================================================================
// Baseline-PTX helpers (NO tcgen05 — harness compiles plain sm_103)
// ============================================================================
__device__ __forceinline__ uint32_t smem_to_u32(const void* p) {
    uint32_t a;
    asm("{ .reg .u64 t; cvta.to.shared.u64 t, %1; cvt.u32.u64 %0, t; }"
        : "=r"(a) : "l"(p));
    return a;
}
__device__ __forceinline__ void cp_async16(uint32_t smem_addr, const void* gptr) {
    asm volatile("cp.async.cg.shared.global [%0], [%1], 16;"
                 :: "r"(smem_addr), "l"(gptr) : "memory");
}
__device__ __forceinline__ void cp_commit() {
    asm volatile("cp.async.commit_group;" ::: "memory");
}
template <int N>
__device__ __forceinline__ void cp_wait_group() {
    asm volatile("cp.async.wait_group %0;" :: "n"(N) : "memory");
}
__device__ __forceinline__ void ldsm_x4(uint32_t* r, uint32_t addr) {
    asm volatile("ldmatrix.sync.aligned.m8n8.x4.shared.b16 {%0,%1,%2,%3}, [%4];"
                 : "=r"(r[0]), "=r"(r[1]), "=r"(r[2]), "=r"(r[3]) : "r"(addr));
}
__device__ __forceinline__ void mma_f16(float* d, const uint32_t* a,
                                        uint32_t b0, uint32_t b1) {
    asm volatile(
        "mma.sync.aligned.m16n8k16.row.col.f32.f16.f16.f32 "
        "{%0,%1,%2,%3}, {%4,%5,%6,%7}, {%8,%9}, {%0,%1,%2,%3};"
        : "+f"(d[0]), "+f"(d[1]), "+f"(d[2]), "+f"(d[3])
        : "r"(a[0]), "r"(a[1]), "r"(a[2]), "r"(a[3]), "r"(b0), "r"(b1));
}

// ============================================================================
// Kernel 0: convert Wv fp32 -> fp16
// ============================================================================
__global__ __launch_bounds__(256) void wconv_kernel(const float* __restrict__ Wv)
{
    size_t base = ((size_t)blockIdx.x * 256 + threadIdx.x) * 8;
    float4 x0 = *reinterpret_cast<const float4*>(Wv + base);
    float4 x1 = *reinterpret_cast<const float4*>(Wv + base + 4);
    float xs[8] = {x0.x, x0.y, x0.z, x0.w, x1.x, x1.y, x1.z, x1.w};
    __half h[8];
    #pragma unroll
    for (int j = 0; j < 8; j++) h[j] = __float2half_rn(xs[j]);
    *reinterpret_cast<uint4*>(g_w + base) = *reinterpret_cast<uint4*>(h);
}

// ============================================================================
// Kernel 1: hash + gather -> fp16 e rows.  One block per token.
// ============================================================================
__global__ __launch_bounds__(256) void gather_kernel(
    const int* __restrict__ input_ids,
    const float* __restrict__ tables2,
    const float* __restrict__ tables3)
{
    int t = blockIdx.x;
    int tid = threadIdx.x;
    __shared__ int s_i2, s_i3;
    if (tid == 0) {
        int b = t / TDIM;
        int tt = t % TDIM;
        const int* row = input_ids + (size_t)b * TDIM;
        int id0 = row[tt];
        id0 = id0 < 0 ? 0 : (id0 > VOCAB - 1 ? VOCAB - 1 : id0);
        int s1 = 0, s2 = 0;
        if (tt >= 1) { s1 = row[tt - 1]; s1 = s1 < 0 ? 0 : (s1 > VOCAB - 1 ? VOCAB - 1 : s1); }
        if (tt >= 2) { s2 = row[tt - 2]; s2 = s2 < 0 ? 0 : (s2 > VOCAB - 1 ? VOCAB - 1 : s2); }
        int hash2 = (id0 * M0) ^ (s1 * M1);
        int hash3 = hash2 ^ (s2 * M2);
        int i2 = hash2 % TS; if (i2 < 0) i2 = 0;
        int i3 = hash3 % TS; if (i3 < 0) i3 = 0;
        s_i2 = i2; s_i3 = i3;
    }
    __syncthreads();
    int i2 = s_i2, i3 = s_i3;

    int f0 = tid * 8;
    int seg = f0 >> 8;
    int off = f0 & 255;
    const float* src = (seg < 4)
        ? tables2 + ((size_t)seg * TS + i2) * 256 + off
        : tables3 + ((size_t)(seg - 4) * TS + i3) * 256 + off;
    float4 x0 = *reinterpret_cast<const float4*>(src);
    float4 x1 = *reinterpret_cast<const float4*>(src + 4);
    float xs[8] = {x0.x, x0.y, x0.z, x0.w, x1.x, x1.y, x1.z, x1.w};
    __half h[8];
    #pragma unroll
    for (int j = 0; j < 8; j++) h[j] = __float2half_rn(xs[j]);
    *reinterpret_cast<uint4*>(g_e + (size_t)t * KDIM + f0) =
        *reinterpret_cast<uint4*>(h);
}

// ============================================================================
// Kernel 2: fp16 GEMM via mma.sync (HMMA), fp32 accum in registers.
//   C[m][n] = sum_k e[m][k] * Wv[n][k]   both K-contiguous (NT)
//   CTA tile 128x128, k-chunk 64 per stage (two 16KB sub-chunks),
//   3-stage cp.async pipeline (distance 2) -> 32 mainloop iterations.
// Stage (32KB): [A_sub0 8KB | B_sub0 8KB | A_sub1 8KB | B_sub1 8KB]
//   each sub: rows x 64B, 16B-unit swizzle c ^= (row>>1)&3.
// ============================================================================
#define NK64 (KDIM / 64)          // 32 iterations
#define STAGES 3
#define STAGE_BYTES 32768
#define SUB_BYTES 16384u
#define GEMM_SMEM (STAGES * STAGE_BYTES)   // 98304

__global__ __launch_bounds__(256, 1) void gemm_kernel()
{
    extern __shared__ char smem[];
    const uint32_t sbase = smem_to_u32(smem);
    const int tid = threadIdx.x;
    const int lane = tid & 31;
    const int wid = tid >> 5;
    const int warpM = wid & 1;        // 2 warps in M
    const int warpN = wid >> 1;       // 4 warps in N
    const int m0 = blockIdx.y * 128;
    const int n0 = blockIdx.x * 128;

    // ---- per-thread cp.async mapping (8 x 16B per stage = k64) ----
    // regions: i=0,1 -> A sub0; 2,3 -> B sub0; 4,5 -> A sub1; 6,7 -> B sub1
    const __half* src[8];
    uint32_t dstoff[8];
    #pragma unroll
    for (int i = 0; i < 8; i++) {
        int g = tid + i * 256;               // 0..2047
        int region = g >> 9;                 // 0..3
        int isB = region & 1;
        int sub = region >> 1;
        int gl = g & 511;
        int row = gl >> 2;                   // 0..127
        int ch = gl & 3;                     // 16B unit within 64B row
        const __half* base = isB ? g_w : g_e;
        int rowg = (isB ? n0 : m0) + row;
        src[i] = base + (size_t)rowg * KDIM + sub * 32 + ch * 8;
        dstoff[i] = (uint32_t)region * 8192u + (uint32_t)row * 64u
                  + (uint32_t)((ch ^ ((row >> 1) & 3)) << 4);
    }

    // ---- ldmatrix address components (verified geometry) ----
    const int l15 = lane & 15;
    const int lhi = lane >> 4;
    const int s = (l15 >> 1) & 3;
    const uint32_t aRowBase = (uint32_t)(warpM * 64 + l15) * 64u;
    const uint32_t bRowBase = 8192u + (uint32_t)(warpN * 32 + l15) * 64u;
    const uint32_t chj[2] = { (uint32_t)((lhi ^ s) << 4),
                              (uint32_t)(((2 + lhi) ^ s) << 4) };

    float acc[4][4][4];
    #pragma unroll
    for (int mf = 0; mf < 4; mf++)
        #pragma unroll
        for (int nf = 0; nf < 4; nf++)
            #pragma unroll
            for (int q = 0; q < 4; q++) acc[mf][nf][q] = 0.f;

    // ---- prologue: preload stages 0, 1 ----
    #pragma unroll
    for (int st = 0; st < 2; st++) {
        uint32_t sb = sbase + st * STAGE_BYTES;
        #pragma unroll
        for (int i = 0; i < 8; i++)
            cp_async16(sb + dstoff[i], src[i] + st * 64);
        cp_commit();
    }

    int buf = 0;
    for (int kt = 0; kt < NK64; kt++) {
        if (kt + 1 < NK64) cp_wait_group<1>(); else cp_wait_group<0>();
        __syncthreads();

        if (kt + 2 < NK64) {
            int nb = buf + 2; if (nb >= STAGES) nb -= STAGES;
            uint32_t sb = sbase + nb * STAGE_BYTES;
            #pragma unroll
            for (int i = 0; i < 8; i++)
                cp_async16(sb + dstoff[i], src[i] + (kt + 2) * 64);
            cp_commit();
        }

        const uint32_t sbst = sbase + buf * STAGE_BYTES;
        #pragma unroll
        for (int sub = 0; sub < 2; sub++) {
            const uint32_t sb = sbst + sub * SUB_BYTES;
            #pragma unroll
            for (int j = 0; j < 2; j++) {    // two k16 halves of each k32 sub
                const uint32_t co = chj[j];
                uint32_t a[4][4];
                uint32_t b[2][4];
                #pragma unroll
                for (int mf = 0; mf < 4; mf++)
                    ldsm_x4(a[mf], sb + aRowBase + (uint32_t)(mf * 1024) + co);
                #pragma unroll
                for (int nh = 0; nh < 2; nh++)
                    ldsm_x4(b[nh], sb + bRowBase + (uint32_t)(nh * 1024) + co);

                #pragma unroll
                for (int mf = 0; mf < 4; mf++)
                    #pragma unroll
                    for (int nf = 0; nf < 4; nf++) {
                        const int nh = nf >> 1, su = nf & 1;
                        mma_f16(acc[mf][nf], a[mf], b[nh][su], b[nh][su + 2]);
                    }
            }
        }
        buf++; if (buf >= STAGES) buf = 0;
    }

    // ---- epilogue: write fp32 result ----
    const int grp = lane >> 2;
    const int q2 = (lane & 3) * 2;
    #pragma unroll
    for (int mf = 0; mf < 4; mf++) {
        #pragma unroll
        for (int nf = 0; nf < 4; nf++) {
            int r = m0 + warpM * 64 + mf * 16 + grp;
            int c = n0 + warpN * 32 + nf * 8 + q2;
            *reinterpret_cast<float2*>(g_v + (size_t)r * DDIM + c) =
                make_float2(acc[mf][nf][0], acc[mf][nf][1]);
            *reinterpret_cast<float2*>(g_v + (size_t)(r + 8) * DDIM + c) =
                make_float2(acc[mf][nf][2], acc[mf][nf][3]);
        }
    }
}

// ============================================================================
// Kernel 3: gating
// ============================================================================
__global__ __launch_bounds__(256) void gate_kernel(
    const float* __restrict__ hidden,
    const float* __restrict__ wh,
    const float* __restrict__ wv,
    float* __restrict__ out)
{
    int t = blockIdx.x;
    int tid = threadIdx.x;
    const float* h = hidden + (size_t)t * DDIM;
    const float* v = g_v + (size_t)t * DDIM;

    float4 v4[2];
    float shh = 0.f, svv = 0.f, shv = 0.f;
    #pragma unroll
    for (int r = 0; r < 2; r++) {
        int q = tid + r * 256;
        float4 h4  = *reinterpret_cast<const float4*>(h + (size_t)q * 4);
        float4 x4  = *reinterpret_cast<const float4*>(v + (size_t)q * 4);
        float4 wh4 = *reinterpret_cast<const float4*>(wh + (size_t)q * 4);
        float4 wv4 = *reinterpret_cast<const float4*>(wv + (size_t)q * 4);
        v4[r] = x4;
        shh += h4.x * h4.x + h4.y * h4.y + h4.z * h4.z + h4.w * h4.w;
        svv += x4.x * x4.x + x4.y * x4.y + x4.z * x4.z + x4.w * x4.w;
        shv += (h4.x * wh4.x) * (x4.x * wv4.x)
             + (h4.y * wh4.y) * (x4.y * wv4.y)
             + (h4.z * wh4.z) * (x4.z * wv4.z)
             + (h4.w * wh4.w) * (x4.w * wv4.w);
    }

    #pragma unroll
    for (int o = 16; o > 0; o >>= 1) {
        shh += __shfl_down_sync(0xffffffffu, shh, o);
        svv += __shfl_down_sync(0xffffffffu, svv, o);
        shv += __shfl_down_sync(0xffffffffu, shv, o);
    }
    __shared__ float s0[8], s1[8], s2[8];
    int warp = tid >> 5, lane = tid & 31;
    if (lane == 0) { s0[warp] = shh; s1[warp] = svv; s2[warp] = shv; }
    __syncthreads();
    float thh = 0.f, tvv = 0.f, thv = 0.f;
    #pragma unroll
    for (int w = 0; w < 8; w++) { thh += s0[w]; tvv += s1[w]; thv += s2[w]; }

    const float eps = 1.1920928955078125e-7f;
    float rh = rsqrtf(thh * (1.f / DDIM) + eps);
    float rv = rsqrtf(tvv * (1.f / DDIM) + eps);
    float gate = thv * rh * rv * (1.f / 45.254833995939045f);
    float ga = fabsf(gate);
    ga = fmaxf(ga, 1e-6f);
    float gs = copysignf(sqrtf(ga), gate);
    float sig = 1.f / (1.f + expf(-gs));

    float* o = out + (size_t)t * DDIM;
    #pragma unroll
    for (int r = 0; r < 2; r++) {
        int q = tid + r * 256;
        float4 x = v4[r];
        x.x *= sig; x.y *= sig; x.z *= sig; x.w *= sig;
        *reinterpret_cast<float4*>(o + (size_t)q * 4) = x;
    }
}

// ---------------------------------------------------------------------------
extern "C" void kernel_launch(void* const* d_in, const int* in_sizes, int n_in,
                              void* d_out, int out_size)
{
    const float* hidden  = (const float*)d_in[0];
    const float* tables2 = (const float*)d_in[1];
    const float* tables3 = (const float*)d_in[2];
    const float* Wv      = (const float*)d_in[3];
    const float* wh      = (const float*)d_in[4];
    const float* wv      = (const float*)d_in[5];
    const int*   ids     = (const int*)d_in[6];
    float* out = (float*)d_out;

    static bool attr_set = false;
    if (!attr_set) {
        cudaFuncSetAttribute(gemm_kernel,
                             cudaFuncAttributeMaxDynamicSharedMemorySize, GEMM_SMEM);
        attr_set = true;
    }

    wconv_kernel<<<(DDIM * KDIM) / (256 * 8), 256>>>(Wv);
    gather_kernel<<<NTOK, 256>>>(ids, tables2, tables3);

    dim3 grid(DDIM / 128, NTOK / 128);   // (16, 128); x-major shares A in L2
    gemm_kernel<<<grid, 256, GEMM_SMEM>>>();

    gate_kernel<<<NTOK, 256>>>(hidden, wh, wv, out);
}

// round 11
// speedup vs baseline: 1.6555x; 1.0003x over previous
#include <cuda_runtime.h>
#include <cuda_fp16.h>
#include <cstdint>

// ---- problem constants ----
#define BDIM 4
#define TDIM 4096
#define NTOK (BDIM * TDIM)      // 16384
#define DDIM 2048
#define KDIM 2048               // H*2*E
#define TS 100000
#define VOCAB 50257
#define M0 20011
#define M1 30011
#define M2 40009

// ---- device scratch (allocation-free rule) ----
__device__ __half g_e[(size_t)NTOK * KDIM];
__device__ __half g_w[(size_t)DDIM * KDIM];
__device__ float  g_v[(size_t)NTOK * DDIM];

// ============================================================================
// Baseline-PTX helpers (NO tcgen05 — harness compiles plain sm_103)
// ============================================================================
__device__ __forceinline__ uint32_t smem_to_u32(const void* p) {
    uint32_t a;
    asm("{ .reg .u64 t; cvta.to.shared.u64 t, %1; cvt.u32.u64 %0, t; }"
        : "=r"(a) : "l"(p));
    return a;
}
__device__ __forceinline__ void cp_async16(uint32_t smem_addr, const void* gptr) {
    asm volatile("cp.async.cg.shared.global [%0], [%1], 16;"
                 :: "r"(smem_addr), "l"(gptr) : "memory");
}
__device__ __forceinline__ void cp_commit() {
    asm volatile("cp.async.commit_group;" ::: "memory");
}
template <int N>
__device__ __forceinline__ void cp_wait_group() {
    asm volatile("cp.async.wait_group %0;" :: "n"(N) : "memory");
}
__device__ __forceinline__ void ldsm_x4(uint32_t* r, uint32_t addr) {
    asm volatile("ldmatrix.sync.aligned.m8n8.x4.shared.b16 {%0,%1,%2,%3}, [%4];"
                 : "=r"(r[0]), "=r"(r[1]), "=r"(r[2]), "=r"(r[3]) : "r"(addr));
}
__device__ __forceinline__ void mma_f16(float* d, const uint32_t* a,
                                        uint32_t b0, uint32_t b1) {
    asm volatile(
        "mma.sync.aligned.m16n8k16.row.col.f32.f16.f16.f32 "
        "{%0,%1,%2,%3}, {%4,%5,%6,%7}, {%8,%9}, {%0,%1,%2,%3};"
        : "+f"(d[0]), "+f"(d[1]), "+f"(d[2]), "+f"(d[3])
        : "r"(a[0]), "r"(a[1]), "r"(a[2]), "r"(a[3]), "r"(b0), "r"(b1));
}

// ============================================================================
// Kernel 0: convert Wv fp32 -> fp16
// ============================================================================
__global__ __launch_bounds__(256) void wconv_kernel(const float* __restrict__ Wv)
{
    size_t base = ((size_t)blockIdx.x * 256 + threadIdx.x) * 8;
    float4 x0 = *reinterpret_cast<const float4*>(Wv + base);
    float4 x1 = *reinterpret_cast<const float4*>(Wv + base + 4);
    float xs[8] = {x0.x, x0.y, x0.z, x0.w, x1.x, x1.y, x1.z, x1.w};
    __half h[8];
    #pragma unroll
    for (int j = 0; j < 8; j++) h[j] = __float2half_rn(xs[j]);
    *reinterpret_cast<uint4*>(g_w + base) = *reinterpret_cast<uint4*>(h);
}

// ============================================================================
// Kernel 1: hash + gather -> fp16 e rows.  One block per token.
// ============================================================================
__global__ __launch_bounds__(256) void gather_kernel(
    const int* __restrict__ input_ids,
    const float* __restrict__ tables2,
    const float* __restrict__ tables3)
{
    int t = blockIdx.x;
    int tid = threadIdx.x;
    __shared__ int s_i2, s_i3;
    if (tid == 0) {
        int b = t / TDIM;
        int tt = t % TDIM;
        const int* row = input_ids + (size_t)b * TDIM;
        int id0 = row[tt];
        id0 = id0 < 0 ? 0 : (id0 > VOCAB - 1 ? VOCAB - 1 : id0);
        int s1 = 0, s2 = 0;
        if (tt >= 1) { s1 = row[tt - 1]; s1 = s1 < 0 ? 0 : (s1 > VOCAB - 1 ? VOCAB - 1 : s1); }
        if (tt >= 2) { s2 = row[tt - 2]; s2 = s2 < 0 ? 0 : (s2 > VOCAB - 1 ? VOCAB - 1 : s2); }
        int hash2 = (id0 * M0) ^ (s1 * M1);
        int hash3 = hash2 ^ (s2 * M2);
        int i2 = hash2 % TS; if (i2 < 0) i2 = 0;
        int i3 = hash3 % TS; if (i3 < 0) i3 = 0;
        s_i2 = i2; s_i3 = i3;
    }
    __syncthreads();
    int i2 = s_i2, i3 = s_i3;

    int f0 = tid * 8;
    int seg = f0 >> 8;
    int off = f0 & 255;
    const float* src = (seg < 4)
        ? tables2 + ((size_t)seg * TS + i2) * 256 + off
        : tables3 + ((size_t)(seg - 4) * TS + i3) * 256 + off;
    float4 x0 = *reinterpret_cast<const float4*>(src);
    float4 x1 = *reinterpret_cast<const float4*>(src + 4);
    float xs[8] = {x0.x, x0.y, x0.z, x0.w, x1.x, x1.y, x1.z, x1.w};
    __half h[8];
    #pragma unroll
    for (int j = 0; j < 8; j++) h[j] = __float2half_rn(xs[j]);
    *reinterpret_cast<uint4*>(g_e + (size_t)t * KDIM + f0) =
        *reinterpret_cast<uint4*>(h);
}

// ============================================================================
// Kernel 2: fp16 GEMM via mma.sync (HMMA), fp32 accum in registers.
//   C[m][n] = sum_k e[m][k] * Wv[n][k]   both K-contiguous (NT)
//   CTA tile 128x128, k-chunk 64 per stage (two 16KB sub-chunks),
//   3-stage cp.async pipeline (distance 2), 32 mainloop iterations.
//   NEW: double-buffered fragment pipeline — LDSM of k16-group g+1 issued
//   before MMAs of group g, hiding shared-load latency behind tensor issue.
// Stage (32KB): [A_sub0 8KB | B_sub0 8KB | A_sub1 8KB | B_sub1 8KB]
//   each sub: rows x 64B, 16B-unit swizzle c ^= (row>>1)&3.
// ============================================================================
#define NK64 (KDIM / 64)          // 32 iterations
#define STAGES 3
#define STAGE_BYTES 32768
#define SUB_BYTES 16384u
#define GEMM_SMEM (STAGES * STAGE_BYTES)   // 98304

__global__ __launch_bounds__(256, 1) void gemm_kernel()
{
    extern __shared__ char smem[];
    const uint32_t sbase = smem_to_u32(smem);
    const int tid = threadIdx.x;
    const int lane = tid & 31;
    const int wid = tid >> 5;
    const int warpM = wid & 1;        // 2 warps in M
    const int warpN = wid >> 1;       // 4 warps in N
    const int m0 = blockIdx.y * 128;
    const int n0 = blockIdx.x * 128;

    // ---- per-thread cp.async mapping (8 x 16B per stage = k64) ----
    const __half* src[8];
    uint32_t dstoff[8];
    #pragma unroll
    for (int i = 0; i < 8; i++) {
        int g = tid + i * 256;               // 0..2047
        int region = g >> 9;                 // 0: A s0, 1: B s0, 2: A s1, 3: B s1
        int isB = region & 1;
        int sub = region >> 1;
        int gl = g & 511;
        int row = gl >> 2;                   // 0..127
        int ch = gl & 3;
        const __half* base = isB ? g_w : g_e;
        int rowg = (isB ? n0 : m0) + row;
        src[i] = base + (size_t)rowg * KDIM + sub * 32 + ch * 8;
        dstoff[i] = (uint32_t)region * 8192u + (uint32_t)row * 64u
                  + (uint32_t)((ch ^ ((row >> 1) & 3)) << 4);
    }

    // ---- ldmatrix address components (verified geometry) ----
    const int l15 = lane & 15;
    const int lhi = lane >> 4;
    const int s = (l15 >> 1) & 3;
    const uint32_t aRowBase = (uint32_t)(warpM * 64 + l15) * 64u;
    const uint32_t bRowBase = 8192u + (uint32_t)(warpN * 32 + l15) * 64u;
    const uint32_t chj[2] = { (uint32_t)((lhi ^ s) << 4),
                              (uint32_t)(((2 + lhi) ^ s) << 4) };

    float acc[4][4][4];
    #pragma unroll
    for (int mf = 0; mf < 4; mf++)
        #pragma unroll
        for (int nf = 0; nf < 4; nf++)
            #pragma unroll
            for (int q = 0; q < 4; q++) acc[mf][nf][q] = 0.f;

    // double-buffered fragments
    uint32_t afr[2][4][4];
    uint32_t bfr[2][2][4];

    // ---- prologue: preload stages 0, 1 ----
    #pragma unroll
    for (int st = 0; st < 2; st++) {
        uint32_t sb = sbase + st * STAGE_BYTES;
        #pragma unroll
        for (int i = 0; i < 8; i++)
            cp_async16(sb + dstoff[i], src[i] + st * 64);
        cp_commit();
    }

    int buf = 0;
    for (int kt = 0; kt < NK64; kt++) {
        if (kt + 1 < NK64) cp_wait_group<1>(); else cp_wait_group<0>();
        __syncthreads();

        if (kt + 2 < NK64) {
            int nb = buf + 2; if (nb >= STAGES) nb -= STAGES;
            uint32_t sb = sbase + nb * STAGE_BYTES;
            #pragma unroll
            for (int i = 0; i < 8; i++)
                cp_async16(sb + dstoff[i], src[i] + (kt + 2) * 64);
            cp_commit();
        }

        const uint32_t sbst = sbase + buf * STAGE_BYTES;

        // group g (0..3): sub = g>>1, j = g&1; fragment buffer = g&1
        // LDSM group 0, then for each g: LDSM g+1 (alt buf), MMA g.
        {
            const uint32_t sb0 = sbst;           // sub 0
            const uint32_t co0 = chj[0];
            #pragma unroll
            for (int mf = 0; mf < 4; mf++)
                ldsm_x4(afr[0][mf], sb0 + aRowBase + (uint32_t)(mf * 1024) + co0);
            #pragma unroll
            for (int nh = 0; nh < 2; nh++)
                ldsm_x4(bfr[0][nh], sb0 + bRowBase + (uint32_t)(nh * 1024) + co0);
        }
        #pragma unroll
        for (int g = 0; g < 4; g++) {
            const int cur = g & 1;
            if (g < 3) {
                const int nxt = cur ^ 1;
                const uint32_t sbn = sbst + (uint32_t)(((g + 1) >> 1) * SUB_BYTES);
                const uint32_t con = chj[(g + 1) & 1];
                #pragma unroll
                for (int mf = 0; mf < 4; mf++)
                    ldsm_x4(afr[nxt][mf], sbn + aRowBase + (uint32_t)(mf * 1024) + con);
                #pragma unroll
                for (int nh = 0; nh < 2; nh++)
                    ldsm_x4(bfr[nxt][nh], sbn + bRowBase + (uint32_t)(nh * 1024) + con);
            }
            #pragma unroll
            for (int mf = 0; mf < 4; mf++)
                #pragma unroll
                for (int nf = 0; nf < 4; nf++) {
                    const int nh = nf >> 1, su = nf & 1;
                    mma_f16(acc[mf][nf], afr[cur][mf],
                            bfr[cur][nh][su], bfr[cur][nh][su + 2]);
                }
        }
        buf++; if (buf >= STAGES) buf = 0;
    }

    // ---- epilogue: write fp32 result ----
    const int grp = lane >> 2;
    const int q2 = (lane & 3) * 2;
    #pragma unroll
    for (int mf = 0; mf < 4; mf++) {
        #pragma unroll
        for (int nf = 0; nf < 4; nf++) {
            int r = m0 + warpM * 64 + mf * 16 + grp;
            int c = n0 + warpN * 32 + nf * 8 + q2;
            *reinterpret_cast<float2*>(g_v + (size_t)r * DDIM + c) =
                make_float2(acc[mf][nf][0], acc[mf][nf][1]);
            *reinterpret_cast<float2*>(g_v + (size_t)(r + 8) * DDIM + c) =
                make_float2(acc[mf][nf][2], acc[mf][nf][3]);
        }
    }
}

// ============================================================================
// Kernel 3: gating
// ============================================================================
__global__ __launch_bounds__(256) void gate_kernel(
    const float* __restrict__ hidden,
    const float* __restrict__ wh,
    const float* __restrict__ wv,
    float* __restrict__ out)
{
    int t = blockIdx.x;
    int tid = threadIdx.x;
    const float* h = hidden + (size_t)t * DDIM;
    const float* v = g_v + (size_t)t * DDIM;

    float4 v4[2];
    float shh = 0.f, svv = 0.f, shv = 0.f;
    #pragma unroll
    for (int r = 0; r < 2; r++) {
        int q = tid + r * 256;
        float4 h4  = *reinterpret_cast<const float4*>(h + (size_t)q * 4);
        float4 x4  = *reinterpret_cast<const float4*>(v + (size_t)q * 4);
        float4 wh4 = *reinterpret_cast<const float4*>(wh + (size_t)q * 4);
        float4 wv4 = *reinterpret_cast<const float4*>(wv + (size_t)q * 4);
        v4[r] = x4;
        shh += h4.x * h4.x + h4.y * h4.y + h4.z * h4.z + h4.w * h4.w;
        svv += x4.x * x4.x + x4.y * x4.y + x4.z * x4.z + x4.w * x4.w;
        shv += (h4.x * wh4.x) * (x4.x * wv4.x)
             + (h4.y * wh4.y) * (x4.y * wv4.y)
             + (h4.z * wh4.z) * (x4.z * wv4.z)
             + (h4.w * wh4.w) * (x4.w * wv4.w);
    }

    #pragma unroll
    for (int o = 16; o > 0; o >>= 1) {
        shh += __shfl_down_sync(0xffffffffu, shh, o);
        svv += __shfl_down_sync(0xffffffffu, svv, o);
        shv += __shfl_down_sync(0xffffffffu, shv, o);
    }
    __shared__ float s0[8], s1[8], s2[8];
    int warp = tid >> 5, lane = tid & 31;
    if (lane == 0) { s0[warp] = shh; s1[warp] = svv; s2[warp] = shv; }
    __syncthreads();
    float thh = 0.f, tvv = 0.f, thv = 0.f;
    #pragma unroll
    for (int w = 0; w < 8; w++) { thh += s0[w]; tvv += s1[w]; thv += s2[w]; }

    const float eps = 1.1920928955078125e-7f;
    float rh = rsqrtf(thh * (1.f / DDIM) + eps);
    float rv = rsqrtf(tvv * (1.f / DDIM) + eps);
    float gate = thv * rh * rv * (1.f / 45.254833995939045f);
    float ga = fabsf(gate);
    ga = fmaxf(ga, 1e-6f);
    float gs = copysignf(sqrtf(ga), gate);
    float sig = 1.f / (1.f + expf(-gs));

    float* o = out + (size_t)t * DDIM;
    #pragma unroll
    for (int r = 0; r < 2; r++) {
        int q = tid + r * 256;
        float4 x = v4[r];
        x.x *= sig; x.y *= sig; x.z *= sig; x.w *= sig;
        *reinterpret_cast<float4*>(o + (size_t)q * 4) = x;
    }
}

// ---------------------------------------------------------------------------
extern "C" void kernel_launch(void* const* d_in, const int* in_sizes, int n_in,
                              void* d_out, int out_size)
{
    const float* hidden  = (const float*)d_in[0];
    const float* tables2 = (const float*)d_in[1];
    const float* tables3 = (const float*)d_in[2];
    const float* Wv      = (const float*)d_in[3];
    const float* wh      = (const float*)d_in[4];
    const float* wv      = (const float*)d_in[5];
    const int*   ids     = (const int*)d_in[6];
    float* out = (float*)d_out;

    static bool attr_set = false;
    if (!attr_set) {
        cudaFuncSetAttribute(gemm_kernel,
                             cudaFuncAttributeMaxDynamicSharedMemorySize, GEMM_SMEM);
        attr_set = true;
    }

    wconv_kernel<<<(DDIM * KDIM) / (256 * 8), 256>>>(Wv);
    gather_kernel<<<NTOK, 256>>>(ids, tables2, tables3);

    dim3 grid(DDIM / 128, NTOK / 128);   // (16, 128); x-major shares A in L2
    gemm_kernel<<<grid, 256, GEMM_SMEM>>>();

    gate_kernel<<<NTOK, 256>>>(hidden, wh, wv, out);
}

// round 14
// speedup vs baseline: 1.7741x; 1.0716x over previous
#include <cuda_runtime.h>
#include <cuda_fp16.h>
#include <cstdint>

// ---- problem constants ----
#define BDIM 4
#define TDIM 4096
#define NTOK (BDIM * TDIM)      // 16384
#define DDIM 2048
#define KDIM 2048               // H*2*E
#define TS 100000
#define VOCAB 50257
#define M0 20011
#define M1 30011
#define M2 40009

// ---- device scratch (allocation-free rule) ----
__device__ __half g_e[(size_t)NTOK * KDIM];
__device__ __half g_w[(size_t)DDIM * KDIM];
__device__ __half g_v[(size_t)NTOK * DDIM];     // v in fp16

// ============================================================================
// Baseline-PTX helpers (NO tcgen05 — harness compiles plain sm_103)
// ============================================================================
__device__ __forceinline__ uint32_t smem_to_u32(const void* p) {
    uint32_t a;
    asm("{ .reg .u64 t; cvta.to.shared.u64 t, %1; cvt.u32.u64 %0, t; }"
        : "=r"(a) : "l"(p));
    return a;
}
__device__ __forceinline__ void cp_async16(uint32_t smem_addr, const void* gptr) {
    asm volatile("cp.async.cg.shared.global [%0], [%1], 16;"
                 :: "r"(smem_addr), "l"(gptr) : "memory");
}
__device__ __forceinline__ void cp_commit() {
    asm volatile("cp.async.commit_group;" ::: "memory");
}
template <int N>
__device__ __forceinline__ void cp_wait_group() {
    asm volatile("cp.async.wait_group %0;" :: "n"(N) : "memory");
}
__device__ __forceinline__ void ldsm_x4(uint32_t* r, uint32_t addr) {
    asm volatile("ldmatrix.sync.aligned.m8n8.x4.shared.b16 {%0,%1,%2,%3}, [%4];"
                 : "=r"(r[0]), "=r"(r[1]), "=r"(r[2]), "=r"(r[3]) : "r"(addr));
}
__device__ __forceinline__ void mma_f16(float* d, const uint32_t* a,
                                        uint32_t b0, uint32_t b1) {
    asm volatile(
        "mma.sync.aligned.m16n8k16.row.col.f32.f16.f16.f32 "
        "{%0,%1,%2,%3}, {%4,%5,%6,%7}, {%8,%9}, {%0,%1,%2,%3};"
        : "+f"(d[0]), "+f"(d[1]), "+f"(d[2]), "+f"(d[3])
        : "r"(a[0]), "r"(a[1]), "r"(a[2]), "r"(a[3]), "r"(b0), "r"(b1));
}

// ============================================================================
// Kernel 0: convert Wv fp32 -> fp16
// ============================================================================
__global__ __launch_bounds__(256) void wconv_kernel(const float* __restrict__ Wv)
{
    size_t base = ((size_t)blockIdx.x * 256 + threadIdx.x) * 8;
    float4 x0 = *reinterpret_cast<const float4*>(Wv + base);
    float4 x1 = *reinterpret_cast<const float4*>(Wv + base + 4);
    float xs[8] = {x0.x, x0.y, x0.z, x0.w, x1.x, x1.y, x1.z, x1.w};
    __half h[8];
    #pragma unroll
    for (int j = 0; j < 8; j++) h[j] = __float2half_rn(xs[j]);
    *reinterpret_cast<uint4*>(g_w + base) = *reinterpret_cast<uint4*>(h);
}

// ============================================================================
// Kernel 1: hash + gather -> fp16 e rows.  One block per token.
// ============================================================================
__global__ __launch_bounds__(256) void gather_kernel(
    const int* __restrict__ input_ids,
    const float* __restrict__ tables2,
    const float* __restrict__ tables3)
{
    int t = blockIdx.x;
    int tid = threadIdx.x;
    __shared__ int s_i2, s_i3;
    if (tid == 0) {
        int b = t / TDIM;
        int tt = t % TDIM;
        const int* row = input_ids + (size_t)b * TDIM;
        int id0 = row[tt];
        id0 = id0 < 0 ? 0 : (id0 > VOCAB - 1 ? VOCAB - 1 : id0);
        int s1 = 0, s2 = 0;
        if (tt >= 1) { s1 = row[tt - 1]; s1 = s1 < 0 ? 0 : (s1 > VOCAB - 1 ? VOCAB - 1 : s1); }
        if (tt >= 2) { s2 = row[tt - 2]; s2 = s2 < 0 ? 0 : (s2 > VOCAB - 1 ? VOCAB - 1 : s2); }
        int hash2 = (id0 * M0) ^ (s1 * M1);
        int hash3 = hash2 ^ (s2 * M2);
        int i2 = hash2 % TS; if (i2 < 0) i2 = 0;
        int i3 = hash3 % TS; if (i3 < 0) i3 = 0;
        s_i2 = i2; s_i3 = i3;
    }
    __syncthreads();
    int i2 = s_i2, i3 = s_i3;

    int f0 = tid * 8;
    int seg = f0 >> 8;
    int off = f0 & 255;
    const float* src = (seg < 4)
        ? tables2 + ((size_t)seg * TS + i2) * 256 + off
        : tables3 + ((size_t)(seg - 4) * TS + i3) * 256 + off;
    float4 x0 = *reinterpret_cast<const float4*>(src);
    float4 x1 = *reinterpret_cast<const float4*>(src + 4);
    float xs[8] = {x0.x, x0.y, x0.z, x0.w, x1.x, x1.y, x1.z, x1.w};
    __half h[8];
    #pragma unroll
    for (int j = 0; j < 8; j++) h[j] = __float2half_rn(xs[j]);
    *reinterpret_cast<uint4*>(g_e + (size_t)t * KDIM + f0) =
        *reinterpret_cast<uint4*>(h);
}

// ============================================================================
// Kernel 2: fp16 GEMM via mma.sync (HMMA), fp32 accum in registers.
//   C[m][n] = sum_k e[m][k] * Wv[n][k]   both K-contiguous (NT)
//   CTA tile 128(M) x 64(N), 128 threads = 4 warps (2M x 2N), warp tile 64x32.
//   k-chunk 32, 4-stage cp.async pipeline (distance 3).
//   __launch_bounds__(128, 2): 256-reg budget (no spills), 2-3 CTAs/SM ->
//   each SMSP holds warps from INDEPENDENT CTAs to hide barrier bubbles.
// Stage (12KB): A @0: 128 rows x 64B; B @8192: 64 rows x 64B.
//   16B-unit swizzle: c ^= (row>>1)&3.
// ============================================================================
#define NK (KDIM / 32)            // 64 chunks
#define STAGES 4
#define STAGE_BYTES 12288
#define B_OFF 8192u
#define GEMM_SMEM (STAGES * STAGE_BYTES)   // 49152

__global__ __launch_bounds__(128, 2) void gemm_kernel()
{
    extern __shared__ char smem[];
    const uint32_t sbase = smem_to_u32(smem);
    const int tid = threadIdx.x;
    const int lane = tid & 31;
    const int wid = tid >> 5;
    const int warpM = wid & 1;        // 2 warps in M
    const int warpN = wid >> 1;       // 2 warps in N
    const int m0 = blockIdx.y * 128;
    const int n0 = blockIdx.x * 64;

    // ---- per-thread cp.async mapping (6 x 16B per stage) ----
    const __half* src[6];
    uint32_t dstoff[6];
    #pragma unroll
    for (int i = 0; i < 6; i++) {
        int g = tid + i * 128;               // 0..767
        int isB = g >= 512;
        int gl = isB ? (g - 512) : g;        // A: 0..511, B: 0..255
        int row = gl >> 2;                   // A: 0..127, B: 0..63
        int ch = gl & 3;                     // 16B unit within 64B row
        const __half* base = isB ? g_w : g_e;
        int rowg = (isB ? n0 : m0) + row;
        src[i] = base + (size_t)rowg * KDIM + ch * 8;
        dstoff[i] = (isB ? B_OFF : 0u) + (uint32_t)row * 64u
                  + (uint32_t)((ch ^ ((row >> 1) & 3)) << 4);
    }

    // ---- ldmatrix address components (verified geometry) ----
    const int l15 = lane & 15;
    const int lhi = lane >> 4;
    const int s = (l15 >> 1) & 3;
    const uint32_t aRowBase = (uint32_t)(warpM * 64 + l15) * 64u;
    const uint32_t bRowBase = B_OFF + (uint32_t)(warpN * 32 + l15) * 64u;
    const uint32_t chj[2] = { (uint32_t)((lhi ^ s) << 4),
                              (uint32_t)(((2 + lhi) ^ s) << 4) };

    float acc[4][4][4];
    #pragma unroll
    for (int mf = 0; mf < 4; mf++)
        #pragma unroll
        for (int nf = 0; nf < 4; nf++)
            #pragma unroll
            for (int q = 0; q < 4; q++) acc[mf][nf][q] = 0.f;

    // ---- prologue: preload stages 0..2 ----
    #pragma unroll
    for (int st = 0; st < 3; st++) {
        uint32_t sb = sbase + st * STAGE_BYTES;
        #pragma unroll
        for (int i = 0; i < 6; i++)
            cp_async16(sb + dstoff[i], src[i] + st * 32);
        cp_commit();
    }

    for (int kt = 0; kt < NK; kt++) {
        if (kt <= NK - 3)      cp_wait_group<2>();
        else if (kt == NK - 2) cp_wait_group<1>();
        else                   cp_wait_group<0>();
        __syncthreads();

        if (kt + 3 < NK) {
            uint32_t sb = sbase + ((kt + 3) & 3) * STAGE_BYTES;
            #pragma unroll
            for (int i = 0; i < 6; i++)
                cp_async16(sb + dstoff[i], src[i] + (kt + 3) * 32);
            cp_commit();
        }

        const uint32_t sb = sbase + (kt & 3) * STAGE_BYTES;
        #pragma unroll
        for (int j = 0; j < 2; j++) {        // two k16 halves of the k32 chunk
            const uint32_t co = chj[j];
            uint32_t a[4][4];
            uint32_t b[2][4];
            #pragma unroll
            for (int mf = 0; mf < 4; mf++)
                ldsm_x4(a[mf], sb + aRowBase + (uint32_t)(mf * 1024) + co);
            #pragma unroll
            for (int nh = 0; nh < 2; nh++)
                ldsm_x4(b[nh], sb + bRowBase + (uint32_t)(nh * 1024) + co);

            #pragma unroll
            for (int mf = 0; mf < 4; mf++)
                #pragma unroll
                for (int nf = 0; nf < 4; nf++) {
                    const int nh = nf >> 1, su = nf & 1;
                    mma_f16(acc[mf][nf], a[mf], b[nh][su], b[nh][su + 2]);
                }
        }
    }

    // ---- epilogue: write fp16 result ----
    const int grp = lane >> 2;
    const int q2 = (lane & 3) * 2;
    #pragma unroll
    for (int mf = 0; mf < 4; mf++) {
        #pragma unroll
        for (int nf = 0; nf < 4; nf++) {
            int r = m0 + warpM * 64 + mf * 16 + grp;
            int c = n0 + warpN * 32 + nf * 8 + q2;
            __half2 v0 = __floats2half2_rn(acc[mf][nf][0], acc[mf][nf][1]);
            __half2 v1 = __floats2half2_rn(acc[mf][nf][2], acc[mf][nf][3]);
            *reinterpret_cast<__half2*>(g_v + (size_t)r * DDIM + c) = v0;
            *reinterpret_cast<__half2*>(g_v + (size_t)(r + 8) * DDIM + c) = v1;
        }
    }
}

// ============================================================================
// Kernel 3: gating.  One block per token, 256 threads, 8 elems/thread.
// v is fp16; everything else fp32.
// ============================================================================
__global__ __launch_bounds__(256) void gate_kernel(
    const float* __restrict__ hidden,
    const float* __restrict__ wh,
    const float* __restrict__ wv,
    float* __restrict__ out)
{
    int t = blockIdx.x;
    int tid = threadIdx.x;
    int idx = tid * 8;
    const float* h = hidden + (size_t)t * DDIM + idx;
    const __half* v = g_v + (size_t)t * DDIM + idx;

    float4 h0 = *reinterpret_cast<const float4*>(h);
    float4 h1 = *reinterpret_cast<const float4*>(h + 4);
    uint4 vp = *reinterpret_cast<const uint4*>(v);
    float4 w0 = *reinterpret_cast<const float4*>(wh + idx);
    float4 w1 = *reinterpret_cast<const float4*>(wh + idx + 4);
    float4 u0 = *reinterpret_cast<const float4*>(wv + idx);
    float4 u1 = *reinterpret_cast<const float4*>(wv + idx + 4);

    float hx[8] = {h0.x, h0.y, h0.z, h0.w, h1.x, h1.y, h1.z, h1.w};
    float whx[8] = {w0.x, w0.y, w0.z, w0.w, w1.x, w1.y, w1.z, w1.w};
    float wvx[8] = {u0.x, u0.y, u0.z, u0.w, u1.x, u1.y, u1.z, u1.w};
    float vx[8];
    {
        const uint32_t* p = reinterpret_cast<const uint32_t*>(&vp);
        #pragma unroll
        for (int k = 0; k < 4; k++) {
            float2 f = __half22float2(*reinterpret_cast<const __half2*>(p + k));
            vx[k * 2] = f.x; vx[k * 2 + 1] = f.y;
        }
    }

    float shh = 0.f, svv = 0.f, shv = 0.f;
    #pragma unroll
    for (int j = 0; j < 8; j++) {
        shh += hx[j] * hx[j];
        svv += vx[j] * vx[j];
        shv += (hx[j] * whx[j]) * (vx[j] * wvx[j]);
    }

    #pragma unroll
    for (int o = 16; o > 0; o >>= 1) {
        shh += __shfl_down_sync(0xffffffffu, shh, o);
        svv += __shfl_down_sync(0xffffffffu, svv, o);
        shv += __shfl_down_sync(0xffffffffu, shv, o);
    }
    __shared__ float s0[8], s1[8], s2[8];
    int warp = tid >> 5, lane = tid & 31;
    if (lane == 0) { s0[warp] = shh; s1[warp] = svv; s2[warp] = shv; }
    __syncthreads();
    float thh = 0.f, tvv = 0.f, thv = 0.f;
    #pragma unroll
    for (int w = 0; w < 8; w++) { thh += s0[w]; tvv += s1[w]; thv += s2[w]; }

    const float eps = 1.1920928955078125e-7f;
    float rh = rsqrtf(thh * (1.f / DDIM) + eps);
    float rv = rsqrtf(tvv * (1.f / DDIM) + eps);
    float gate = thv * rh * rv * (1.f / 45.254833995939045f);
    float ga = fabsf(gate);
    ga = fmaxf(ga, 1e-6f);
    float gs = copysignf(sqrtf(ga), gate);
    float sig = 1.f / (1.f + expf(-gs));

    float* o = out + (size_t)t * DDIM + idx;
    float4 o0 = make_float4(vx[0] * sig, vx[1] * sig, vx[2] * sig, vx[3] * sig);
    float4 o1 = make_float4(vx[4] * sig, vx[5] * sig, vx[6] * sig, vx[7] * sig);
    *reinterpret_cast<float4*>(o)     = o0;
    *reinterpret_cast<float4*>(o + 4) = o1;
}

// ---------------------------------------------------------------------------
extern "C" void kernel_launch(void* const* d_in, const int* in_sizes, int n_in,
                              void* d_out, int out_size)
{
    const float* hidden  = (const float*)d_in[0];
    const float* tables2 = (const float*)d_in[1];
    const float* tables3 = (const float*)d_in[2];
    const float* Wv      = (const float*)d_in[3];
    const float* wh      = (const float*)d_in[4];
    const float* wv      = (const float*)d_in[5];
    const int*   ids     = (const int*)d_in[6];
    float* out = (float*)d_out;

    static bool attr_set = false;
    if (!attr_set) {
        cudaFuncSetAttribute(gemm_kernel,
                             cudaFuncAttributeMaxDynamicSharedMemorySize, GEMM_SMEM);
        attr_set = true;
    }

    wconv_kernel<<<(DDIM * KDIM) / (256 * 8), 256>>>(Wv);
    gather_kernel<<<NTOK, 256>>>(ids, tables2, tables3);

    dim3 grid(DDIM / 64, NTOK / 128);   // (32, 128); x-major shares A in L2
    gemm_kernel<<<grid, 128, GEMM_SMEM>>>();

    gate_kernel<<<NTOK, 256>>>(hidden, wh, wv, out);
}

// round 15
// speedup vs baseline: 1.7762x; 1.0012x over previous
#include <cuda_runtime.h>
#include <cuda_fp16.h>
#include <cstdint>

// ---- problem constants ----
#define BDIM 4
#define TDIM 4096
#define NTOK (BDIM * TDIM)      // 16384
#define DDIM 2048
#define KDIM 2048               // H*2*E
#define TS 100000
#define VOCAB 50257
#define M0 20011
#define M1 30011
#define M2 40009

// ---- device scratch (allocation-free rule) ----
__device__ __half g_e[(size_t)NTOK * KDIM];
__device__ __half g_w[(size_t)DDIM * KDIM];
__device__ __half g_v[(size_t)NTOK * DDIM];     // v in fp16

// ============================================================================
// Baseline-PTX helpers (NO tcgen05 — harness compiles plain sm_103)
// ============================================================================
__device__ __forceinline__ uint32_t smem_to_u32(const void* p) {
    uint32_t a;
    asm("{ .reg .u64 t; cvta.to.shared.u64 t, %1; cvt.u32.u64 %0, t; }"
        : "=r"(a) : "l"(p));
    return a;
}
__device__ __forceinline__ void cp_async16(uint32_t smem_addr, const void* gptr) {
    asm volatile("cp.async.cg.shared.global [%0], [%1], 16;"
                 :: "r"(smem_addr), "l"(gptr) : "memory");
}
__device__ __forceinline__ void cp_commit() {
    asm volatile("cp.async.commit_group;" ::: "memory");
}
template <int N>
__device__ __forceinline__ void cp_wait_group() {
    asm volatile("cp.async.wait_group %0;" :: "n"(N) : "memory");
}
__device__ __forceinline__ void ldsm_x4(uint32_t* r, uint32_t addr) {
    asm volatile("ldmatrix.sync.aligned.m8n8.x4.shared.b16 {%0,%1,%2,%3}, [%4];"
                 : "=r"(r[0]), "=r"(r[1]), "=r"(r[2]), "=r"(r[3]) : "r"(addr));
}
__device__ __forceinline__ void mma_f16(float* d, const uint32_t* a,
                                        uint32_t b0, uint32_t b1) {
    asm volatile(
        "mma.sync.aligned.m16n8k16.row.col.f32.f16.f16.f32 "
        "{%0,%1,%2,%3}, {%4,%5,%6,%7}, {%8,%9}, {%0,%1,%2,%3};"
        : "+f"(d[0]), "+f"(d[1]), "+f"(d[2]), "+f"(d[3])
        : "r"(a[0]), "r"(a[1]), "r"(a[2]), "r"(a[3]), "r"(b0), "r"(b1));
}

// ============================================================================
// Kernel 1 (fused prep): blocks [0, NTOK) = hash+gather token rows;
//                        blocks [NTOK, NTOK+DDIM) = convert one Wv row.
// wconv rides inside the gather's DRAM shadow instead of serializing after it.
// ============================================================================
__global__ __launch_bounds__(256) void prep_kernel(
    const int* __restrict__ input_ids,
    const float* __restrict__ tables2,
    const float* __restrict__ tables3,
    const float* __restrict__ Wv)
{
    int blk = blockIdx.x;
    int tid = threadIdx.x;

    if (blk >= NTOK) {
        // ---- Wv row conversion: one row of 2048 floats per block ----
        int row = blk - NTOK;
        size_t base = (size_t)row * KDIM + tid * 8;
        float4 x0 = *reinterpret_cast<const float4*>(Wv + base);
        float4 x1 = *reinterpret_cast<const float4*>(Wv + base + 4);
        float xs[8] = {x0.x, x0.y, x0.z, x0.w, x1.x, x1.y, x1.z, x1.w};
        __half h[8];
        #pragma unroll
        for (int j = 0; j < 8; j++) h[j] = __float2half_rn(xs[j]);
        *reinterpret_cast<uint4*>(g_w + base) = *reinterpret_cast<uint4*>(h);
        return;
    }

    // ---- gather path: one token per block ----
    int t = blk;
    __shared__ int s_i2, s_i3;
    if (tid == 0) {
        int b = t / TDIM;
        int tt = t % TDIM;
        const int* row = input_ids + (size_t)b * TDIM;
        int id0 = row[tt];
        id0 = id0 < 0 ? 0 : (id0 > VOCAB - 1 ? VOCAB - 1 : id0);
        int s1 = 0, s2 = 0;
        if (tt >= 1) { s1 = row[tt - 1]; s1 = s1 < 0 ? 0 : (s1 > VOCAB - 1 ? VOCAB - 1 : s1); }
        if (tt >= 2) { s2 = row[tt - 2]; s2 = s2 < 0 ? 0 : (s2 > VOCAB - 1 ? VOCAB - 1 : s2); }
        int hash2 = (id0 * M0) ^ (s1 * M1);
        int hash3 = hash2 ^ (s2 * M2);
        int i2 = hash2 % TS; if (i2 < 0) i2 = 0;
        int i3 = hash3 % TS; if (i3 < 0) i3 = 0;
        s_i2 = i2; s_i3 = i3;
    }
    __syncthreads();
    int i2 = s_i2, i3 = s_i3;

    int f0 = tid * 8;
    int seg = f0 >> 8;
    int off = f0 & 255;
    const float* src = (seg < 4)
        ? tables2 + ((size_t)seg * TS + i2) * 256 + off
        : tables3 + ((size_t)(seg - 4) * TS + i3) * 256 + off;
    float4 x0 = *reinterpret_cast<const float4*>(src);
    float4 x1 = *reinterpret_cast<const float4*>(src + 4);
    float xs[8] = {x0.x, x0.y, x0.z, x0.w, x1.x, x1.y, x1.z, x1.w};
    __half h[8];
    #pragma unroll
    for (int j = 0; j < 8; j++) h[j] = __float2half_rn(xs[j]);
    *reinterpret_cast<uint4*>(g_e + (size_t)t * KDIM + f0) =
        *reinterpret_cast<uint4*>(h);
}

// ============================================================================
// Kernel 2: fp16 GEMM via mma.sync (HMMA), fp32 accum in registers.
//   C[m][n] = sum_k e[m][k] * Wv[n][k]   both K-contiguous (NT)
//   CTA tile 128(M) x 64(N), 128 threads = 4 warps (2M x 2N), warp tile 64x32.
//   k-chunk 32, 4-stage cp.async pipeline (distance 3).
//   __launch_bounds__(128, 3): reg target 170 (natural ~130, no spills),
//   3 CTAs/SM -> each SMSP holds warps from INDEPENDENT CTAs.
// Stage (12KB): A @0: 128 rows x 64B; B @8192: 64 rows x 64B.
//   16B-unit swizzle: c ^= (row>>1)&3.
// ============================================================================
#define NK (KDIM / 32)            // 64 chunks
#define STAGES 4
#define STAGE_BYTES 12288
#define B_OFF 8192u
#define GEMM_SMEM (STAGES * STAGE_BYTES)   // 49152

__global__ __launch_bounds__(128, 3) void gemm_kernel()
{
    extern __shared__ char smem[];
    const uint32_t sbase = smem_to_u32(smem);
    const int tid = threadIdx.x;
    const int lane = tid & 31;
    const int wid = tid >> 5;
    const int warpM = wid & 1;        // 2 warps in M
    const int warpN = wid >> 1;       // 2 warps in N
    const int m0 = blockIdx.y * 128;
    const int n0 = blockIdx.x * 64;

    // ---- per-thread cp.async mapping (6 x 16B per stage) ----
    const __half* src[6];
    uint32_t dstoff[6];
    #pragma unroll
    for (int i = 0; i < 6; i++) {
        int g = tid + i * 128;               // 0..767
        int isB = g >= 512;
        int gl = isB ? (g - 512) : g;        // A: 0..511, B: 0..255
        int row = gl >> 2;                   // A: 0..127, B: 0..63
        int ch = gl & 3;                     // 16B unit within 64B row
        const __half* base = isB ? g_w : g_e;
        int rowg = (isB ? n0 : m0) + row;
        src[i] = base + (size_t)rowg * KDIM + ch * 8;
        dstoff[i] = (isB ? B_OFF : 0u) + (uint32_t)row * 64u
                  + (uint32_t)((ch ^ ((row >> 1) & 3)) << 4);
    }

    // ---- ldmatrix address components (verified geometry) ----
    const int l15 = lane & 15;
    const int lhi = lane >> 4;
    const int s = (l15 >> 1) & 3;
    const uint32_t aRowBase = (uint32_t)(warpM * 64 + l15) * 64u;
    const uint32_t bRowBase = B_OFF + (uint32_t)(warpN * 32 + l15) * 64u;
    const uint32_t chj[2] = { (uint32_t)((lhi ^ s) << 4),
                              (uint32_t)(((2 + lhi) ^ s) << 4) };

    float acc[4][4][4];
    #pragma unroll
    for (int mf = 0; mf < 4; mf++)
        #pragma unroll
        for (int nf = 0; nf < 4; nf++)
            #pragma unroll
            for (int q = 0; q < 4; q++) acc[mf][nf][q] = 0.f;

    // ---- prologue: preload stages 0..2 ----
    #pragma unroll
    for (int st = 0; st < 3; st++) {
        uint32_t sb = sbase + st * STAGE_BYTES;
        #pragma unroll
        for (int i = 0; i < 6; i++)
            cp_async16(sb + dstoff[i], src[i] + st * 32);
        cp_commit();
    }

    for (int kt = 0; kt < NK; kt++) {
        if (kt <= NK - 3)      cp_wait_group<2>();
        else if (kt == NK - 2) cp_wait_group<1>();
        else                   cp_wait_group<0>();
        __syncthreads();

        if (kt + 3 < NK) {
            uint32_t sb = sbase + ((kt + 3) & 3) * STAGE_BYTES;
            #pragma unroll
            for (int i = 0; i < 6; i++)
                cp_async16(sb + dstoff[i], src[i] + (kt + 3) * 32);
            cp_commit();
        }

        const uint32_t sb = sbase + (kt & 3) * STAGE_BYTES;
        #pragma unroll
        for (int j = 0; j < 2; j++) {        // two k16 halves of the k32 chunk
            const uint32_t co = chj[j];
            uint32_t a[4][4];
            uint32_t b[2][4];
            #pragma unroll
            for (int mf = 0; mf < 4; mf++)
                ldsm_x4(a[mf], sb + aRowBase + (uint32_t)(mf * 1024) + co);
            #pragma unroll
            for (int nh = 0; nh < 2; nh++)
                ldsm_x4(b[nh], sb + bRowBase + (uint32_t)(nh * 1024) + co);

            #pragma unroll
            for (int mf = 0; mf < 4; mf++)
                #pragma unroll
                for (int nf = 0; nf < 4; nf++) {
                    const int nh = nf >> 1, su = nf & 1;
                    mma_f16(acc[mf][nf], a[mf], b[nh][su], b[nh][su + 2]);
                }
        }
    }

    // ---- epilogue: write fp16 result ----
    const int grp = lane >> 2;
    const int q2 = (lane & 3) * 2;
    #pragma unroll
    for (int mf = 0; mf < 4; mf++) {
        #pragma unroll
        for (int nf = 0; nf < 4; nf++) {
            int r = m0 + warpM * 64 + mf * 16 + grp;
            int c = n0 + warpN * 32 + nf * 8 + q2;
            __half2 v0 = __floats2half2_rn(acc[mf][nf][0], acc[mf][nf][1]);
            __half2 v1 = __floats2half2_rn(acc[mf][nf][2], acc[mf][nf][3]);
            *reinterpret_cast<__half2*>(g_v + (size_t)r * DDIM + c) = v0;
            *reinterpret_cast<__half2*>(g_v + (size_t)(r + 8) * DDIM + c) = v1;
        }
    }
}

// ============================================================================
// Kernel 3: gating.  One block per token, 256 threads, 8 elems/thread.
// v is fp16; everything else fp32.
// ============================================================================
__global__ __launch_bounds__(256) void gate_kernel(
    const float* __restrict__ hidden,
    const float* __restrict__ wh,
    const float* __restrict__ wv,
    float* __restrict__ out)
{
    int t = blockIdx.x;
    int tid = threadIdx.x;
    int idx = tid * 8;
    const float* h = hidden + (size_t)t * DDIM + idx;
    const __half* v = g_v + (size_t)t * DDIM + idx;

    float4 h0 = *reinterpret_cast<const float4*>(h);
    float4 h1 = *reinterpret_cast<const float4*>(h + 4);
    uint4 vp = *reinterpret_cast<const uint4*>(v);
    float4 w0 = *reinterpret_cast<const float4*>(wh + idx);
    float4 w1 = *reinterpret_cast<const float4*>(wh + idx + 4);
    float4 u0 = *reinterpret_cast<const float4*>(wv + idx);
    float4 u1 = *reinterpret_cast<const float4*>(wv + idx + 4);

    float hx[8] = {h0.x, h0.y, h0.z, h0.w, h1.x, h1.y, h1.z, h1.w};
    float whx[8] = {w0.x, w0.y, w0.z, w0.w, w1.x, w1.y, w1.z, w1.w};
    float wvx[8] = {u0.x, u0.y, u0.z, u0.w, u1.x, u1.y, u1.z, u1.w};
    float vx[8];
    {
        const uint32_t* p = reinterpret_cast<const uint32_t*>(&vp);
        #pragma unroll
        for (int k = 0; k < 4; k++) {
            float2 f = __half22float2(*reinterpret_cast<const __half2*>(p + k));
            vx[k * 2] = f.x; vx[k * 2 + 1] = f.y;
        }
    }

    float shh = 0.f, svv = 0.f, shv = 0.f;
    #pragma unroll
    for (int j = 0; j < 8; j++) {
        shh += hx[j] * hx[j];
        svv += vx[j] * vx[j];
        shv += (hx[j] * whx[j]) * (vx[j] * wvx[j]);
    }

    #pragma unroll
    for (int o = 16; o > 0; o >>= 1) {
        shh += __shfl_down_sync(0xffffffffu, shh, o);
        svv += __shfl_down_sync(0xffffffffu, svv, o);
        shv += __shfl_down_sync(0xffffffffu, shv, o);
    }
    __shared__ float s0[8], s1[8], s2[8];
    int warp = tid >> 5, lane = tid & 31;
    if (lane == 0) { s0[warp] = shh; s1[warp] = svv; s2[warp] = shv; }
    __syncthreads();
    float thh = 0.f, tvv = 0.f, thv = 0.f;
    #pragma unroll
    for (int w = 0; w < 8; w++) { thh += s0[w]; tvv += s1[w]; thv += s2[w]; }

    const float eps = 1.1920928955078125e-7f;
    float rh = rsqrtf(thh * (1.f / DDIM) + eps);
    float rv = rsqrtf(tvv * (1.f / DDIM) + eps);
    float gate = thv * rh * rv * (1.f / 45.254833995939045f);
    float ga = fabsf(gate);
    ga = fmaxf(ga, 1e-6f);
    float gs = copysignf(sqrtf(ga), gate);
    float sig = 1.f / (1.f + expf(-gs));

    float* o = out + (size_t)t * DDIM + idx;
    float4 o0 = make_float4(vx[0] * sig, vx[1] * sig, vx[2] * sig, vx[3] * sig);
    float4 o1 = make_float4(vx[4] * sig, vx[5] * sig, vx[6] * sig, vx[7] * sig);
    *reinterpret_cast<float4*>(o)     = o0;
    *reinterpret_cast<float4*>(o + 4) = o1;
}

// ---------------------------------------------------------------------------
extern "C" void kernel_launch(void* const* d_in, const int* in_sizes, int n_in,
                              void* d_out, int out_size)
{
    const float* hidden  = (const float*)d_in[0];
    const float* tables2 = (const float*)d_in[1];
    const float* tables3 = (const float*)d_in[2];
    const float* Wv      = (const float*)d_in[3];
    const float* wh      = (const float*)d_in[4];
    const float* wv      = (const float*)d_in[5];
    const int*   ids     = (const int*)d_in[6];
    float* out = (float*)d_out;

    static bool attr_set = false;
    if (!attr_set) {
        cudaFuncSetAttribute(gemm_kernel,
                             cudaFuncAttributeMaxDynamicSharedMemorySize, GEMM_SMEM);
        attr_set = true;
    }

    prep_kernel<<<NTOK + DDIM, 256>>>(ids, tables2, tables3, Wv);

    dim3 grid(DDIM / 64, NTOK / 128);   // (32, 128); x-major shares A in L2
    gemm_kernel<<<grid, 128, GEMM_SMEM>>>();

    gate_kernel<<<NTOK, 256>>>(hidden, wh, wv, out);
}